// round 12
// baseline (speedup 1.0000x reference)
#include <cuda_runtime.h>
#include <cuda_fp16.h>
#include <math.h>
#include <stdint.h>

#define NN   10000
#define EE   160000
#define SEQL 96
#define HIDC 128
#define NH   8
#define HC   1024   // NH*HIDC
#define OUTC 768

// ---------------- scratch (device globals; no allocation allowed) ----------
__device__ __half g_hw [NN * HC];    // W-transformed features (fp16 messages)
__device__ __half g_act[NN * HC];    // layer activations (fp16, GEMM A input)
__device__ __half g_x16[NN * SEQL];  // x transposed -> fp16 [NN][SEQ]
__device__ __half g_w1 [SEQL * HC];
__device__ __half g_w2 [HC * HC];
__device__ __half g_w3 [HC * OUTC];
__device__ float g_asrc[NN * NH];
__device__ float g_adst[NN * NH];
__device__ float g_ce  [NH];
__device__ int   g_deg [NN];
__device__ int   g_rowptr[NN + 1];
__device__ int   g_cursor[NN];
__device__ int   g_csr[EE];

// ======================= fp16 tensor-core GEMM =============================
// C[M,Ncol] = A @ B, fp16 in, fp32 accum, fp16 out.
// CTA tile 128x128, 256 thr (8 warps, 2x4), warp tile 64x32, K-chunk 32.
// THREE-stage cp.async pipeline (prefetch distance 2); 2 CTAs/SM.

#define SMSA 40      // A row stride in halves (80B; conflict-free ldmatrix)
#define SMSB 136     // B row stride in halves (272B)
#define OFF_A  0
#define OFF_B  10240                 // 128*40*2
#define BUFSZ  18944                 // + 32*136*2
#define NSTAGE 3
#define GSMEM  (NSTAGE * BUFSZ)      // 56832

__device__ __forceinline__ uint32_t sm32(const void* p) {
    return (uint32_t)__cvta_generic_to_shared(p);
}

__device__ __forceinline__ void cp16(uint32_t dst, const void* src, int bytes) {
    asm volatile("cp.async.cg.shared.global [%0], [%1], 16, %2;"
                 :: "r"(dst), "l"(src), "r"(bytes));
}

__device__ __forceinline__ void cp_commit() {
    asm volatile("cp.async.commit_group;");
}

__device__ __forceinline__ void cp_wait2() {
    asm volatile("cp.async.wait_group 2;");
}

__device__ __forceinline__ void ldm_x4(uint32_t* d, uint32_t addr) {
    asm volatile("ldmatrix.sync.aligned.m8n8.x4.shared.b16 {%0,%1,%2,%3}, [%4];"
                 : "=r"(d[0]), "=r"(d[1]), "=r"(d[2]), "=r"(d[3]) : "r"(addr));
}

__device__ __forceinline__ void ldm_x4_t(uint32_t* d, uint32_t addr) {
    asm volatile("ldmatrix.sync.aligned.m8n8.x4.trans.shared.b16 {%0,%1,%2,%3}, [%4];"
                 : "=r"(d[0]), "=r"(d[1]), "=r"(d[2]), "=r"(d[3]) : "r"(addr));
}

__device__ __forceinline__ void mma_fp16(float* c, const uint32_t* a, const uint32_t* b) {
    asm volatile(
        "mma.sync.aligned.m16n8k16.row.col.f32.f16.f16.f32 "
        "{%0,%1,%2,%3},{%4,%5,%6,%7},{%8,%9},{%0,%1,%2,%3};"
        : "+f"(c[0]), "+f"(c[1]), "+f"(c[2]), "+f"(c[3])
        : "r"(a[0]), "r"(a[1]), "r"(a[2]), "r"(a[3]), "r"(b[0]), "r"(b[1]));
}

__global__ __launch_bounds__(256, 2) void gemm_fp16(
    const __half* __restrict__ Ag, const __half* __restrict__ Bg,
    __half* __restrict__ C, int M, int K, int Ncol)
{
    extern __shared__ __align__(16) char dyn[];
    const uint32_t smbase = sm32(dyn);

    const int tid  = threadIdx.x;
    const int lane = tid & 31;
    const int w    = tid >> 5;
    const int wr   = w >> 2, wc = w & 3;      // 2x4 warp grid
    const int m0   = blockIdx.y * 128, n0 = blockIdx.x * 128;
    const int r    = lane >> 2, q = lane & 3;

    float acc[4][4][4];
#pragma unroll
    for (int a = 0; a < 4; a++)
#pragma unroll
        for (int b = 0; b < 4; b++)
#pragma unroll
            for (int i = 0; i < 4; i++) acc[a][b][i] = 0.f;

    const int nchunks = K / 32;

    // ---- cp.async fp16 chunk c -> stage buffer s (ALWAYS commits a group) --
    auto issue = [&](int c, int s) {
        if (c < nchunks) {
            const int k0 = c * 32;
            const uint32_t base = smbase + s * BUFSZ;
#pragma unroll
            for (int i = 0; i < 2; i++) {       // A: 128 rows x 64B
                const int idx = i * 256 + tid;
                const int row = idx >> 2, seg = idx & 3;
                const int gm = m0 + row;
                const size_t go = (size_t)gm * K + k0 + seg * 8;
                cp16(base + OFF_A + row * 80 + seg * 16, &Ag[go], (gm < M) ? 16 : 0);
            }
#pragma unroll
            for (int i = 0; i < 2; i++) {       // B: 32 rows x 256B
                const int idx = i * 256 + tid;
                const int row = idx >> 4, seg = idx & 15;
                const size_t go = (size_t)(k0 + row) * Ncol + n0 + seg * 8;
                cp16(base + OFF_B + row * 272 + seg * 16, &Bg[go], 16);
            }
        }
        cp_commit();
    };

    // fragment base addresses (stage 0)
    uint32_t aaddr[4];
#pragma unroll
    for (int mt = 0; mt < 4; mt++)
        aaddr[mt] = smbase + OFF_A + (wr * 64 + mt * 16 + (lane & 15)) * 80 + (lane >> 4) * 16;
    uint32_t baddr[2];
#pragma unroll
    for (int g = 0; g < 2; g++)
        baddr[g] = smbase + OFF_B + (lane & 15) * 272 + (wc * 32 + g * 16 + 8 * (lane >> 4)) * 2;

    // one K=16 MMA pass
    auto pass = [&](uint32_t boff, int kb) {
        uint32_t af[4][4], bf[2][4];
#pragma unroll
        for (int mt = 0; mt < 4; mt++) ldm_x4(af[mt], aaddr[mt] + boff + kb * 2);
#pragma unroll
        for (int g = 0; g < 2; g++) ldm_x4_t(bf[g], baddr[g] + boff + kb * 272);
#pragma unroll
        for (int mt = 0; mt < 4; mt++)
#pragma unroll
            for (int nt = 0; nt < 4; nt++)
                mma_fp16(acc[mt][nt], af[mt], &bf[nt >> 1][(nt & 1) * 2]);
    };

    issue(0, 0);
    issue(1, 1);
    issue(2, 2);
    int stage = 0;
    for (int c = 0; c < nchunks; c++) {
        const uint32_t boff = stage * BUFSZ;
        cp_wait2();                    // <=2 groups outstanding -> chunk c landed
        __syncthreads();
        pass(boff, 0);
        pass(boff, 16);
        __syncthreads();               // all warps done with this stage buffer
        issue(c + 3, stage);           // refill same stage (distance 3)
        stage = (stage + 1 == NSTAGE) ? 0 : stage + 1;
    }

    // epilogue: fp32 acc -> fp16 store
#pragma unroll
    for (int mt = 0; mt < 4; mt++) {
        const int r0 = m0 + wr * 64 + mt * 16 + r;
        const int r1 = r0 + 8;
#pragma unroll
        for (int nt = 0; nt < 4; nt++) {
            const int col = n0 + wc * 32 + nt * 8 + 2 * q;
            if (r0 < M)
                *(__half2*)&C[(size_t)r0 * Ncol + col] =
                    __floats2half2_rn(acc[mt][nt][0], acc[mt][nt][1]);
            if (r1 < M)
                *(__half2*)&C[(size_t)r1 * Ncol + col] =
                    __floats2half2_rn(acc[mt][nt][2], acc[mt][nt][3]);
        }
    }
}

// ---------------- prep: elementwise fp32 -> fp16 --------------------------
__global__ void conv_w(const float* __restrict__ w, __half* __restrict__ wh, int n)
{
    const int i = blockIdx.x * blockDim.x + threadIdx.x;
    if (i < n) wh[i] = __float2half_rn(w[i]);
}

// ---------------- prep: transpose x [SEQ][NN] -> fp16 [NN][SEQ] -----------
__global__ void transpose_h(const float* __restrict__ x, __half* __restrict__ xh)
{
    __shared__ float sm[32][33];
    const int m0 = blockIdx.x * 32, k0 = blockIdx.y * 32;
    const int tx = threadIdx.x, ty = threadIdx.y;   // 32x8
#pragma unroll
    for (int j = 0; j < 4; j++) {
        const int k = k0 + ty + j * 8, m = m0 + tx;
        sm[ty + j * 8][tx] = (m < NN) ? x[(size_t)k * NN + m] : 0.f;
    }
    __syncthreads();
#pragma unroll
    for (int j = 0; j < 4; j++) {
        const int m = m0 + ty + j * 8, k = k0 + tx;
        if (m < NN) xh[(size_t)m * SEQL + k] = __float2half_rn(sm[tx][ty + j * 8]);
    }
}

// -------- per-node attention dots: one warp per (node, head) ---------------
__global__ void node_dot(const __half* __restrict__ h, const float* __restrict__ ws,
                         const float* __restrict__ wd, float* __restrict__ asrc,
                         float* __restrict__ adst, int C, int H)
{
    const int w    = (blockIdx.x * blockDim.x + threadIdx.x) >> 5;
    const int lane = threadIdx.x & 31;
    if (w >= NN * H) return;
    const int n = w / H, hd = w - n * H;
    const __half* hp = h + (size_t)n * H * C + hd * C;
    float s1 = 0.f, s2 = 0.f;
    for (int c = lane * 2; c < C; c += 64) {
        const float2 v = __half22float2(*(const __half2*)&hp[c]);
        s1 += v.x * ws[hd * C + c] + v.y * ws[hd * C + c + 1];
        s2 += v.x * wd[hd * C + c] + v.y * wd[hd * C + c + 1];
    }
#pragma unroll
    for (int o = 16; o; o >>= 1) {
        s1 += __shfl_down_sync(0xffffffffu, s1, o);
        s2 += __shfl_down_sync(0xffffffffu, s2, o);
    }
    if (lane == 0) { asrc[w] = s1; adst[w] = s2; }
}

__global__ void ce_kernel(const float* __restrict__ We, const float* __restrict__ ae,
                          float* __restrict__ ce, int C, int H)
{
    const int h = threadIdx.x;
    if (h >= H) return;
    float s = 0.f;
    for (int c = 0; c < C; c++) s += We[h * C + c] * ae[h * C + c];
    ce[h] = s;
}

// ======================= CSR build (once per launch) =======================
__global__ void zero_deg(int* __restrict__ deg)
{
    const int i = blockIdx.x * blockDim.x + threadIdx.x;
    if (i < NN) deg[i] = 0;
}

__global__ void count_deg(const int* __restrict__ dst, int* __restrict__ deg)
{
    const int e = blockIdx.x * blockDim.x + threadIdx.x;
    if (e < EE) atomicAdd(&deg[dst[e]], 1);
}

__global__ void scan_rowptr(const int* __restrict__ deg, int* __restrict__ rowptr)
{
    __shared__ int ssum[1024];
    const int t = threadIdx.x;
    const int CHK = (NN + 1023) / 1024;
    const int base = t * CHK;
    int s = 0;
    for (int i = 0; i < CHK; i++) {
        const int idx = base + i;
        if (idx < NN) s += deg[idx];
    }
    ssum[t] = s;
    __syncthreads();
    for (int off = 1; off < 1024; off <<= 1) {
        int v = (t >= off) ? ssum[t - off] : 0;
        __syncthreads();
        ssum[t] += v;
        __syncthreads();
    }
    int run = ssum[t] - s;
    for (int i = 0; i < CHK; i++) {
        const int idx = base + i;
        if (idx < NN) { rowptr[idx] = run; run += deg[idx]; }
    }
    if (t == 0) rowptr[NN] = EE;
}

__global__ void init_cursor(const int* __restrict__ rowptr, int* __restrict__ cursor)
{
    const int i = blockIdx.x * blockDim.x + threadIdx.x;
    if (i < NN) cursor[i] = rowptr[i];
}

__global__ void scatter_csr(const int* __restrict__ dst, int* __restrict__ cursor,
                            int* __restrict__ csr)
{
    const int e = blockIdx.x * blockDim.x + threadIdx.x;
    if (e >= EE) return;
    const int pos = atomicAdd(&cursor[dst[e]], 1);
    csr[pos] = e;
}

// == FUSED softmax + CSR aggregation: one block per node, 4 ch/thread =======
// NT threads = TOT/4. Computes logits in-block, exp into smem, per-head den
// accumulated across chunks, single normalize at end.
template <int CPH, int H, bool RELU, bool HALF_OUT>
__global__ void agg_fused(
                        const int* __restrict__ rowptr, const int* __restrict__ csr,
                        const int* __restrict__ src, const __half* __restrict__ hw,
                        const float* __restrict__ asrc, const float* __restrict__ adst,
                        const float* __restrict__ ew, const float* __restrict__ ce,
                        const float* __restrict__ bias, float* __restrict__ out,
                        __half* __restrict__ outh)
{
    constexpr int TOT = CPH * H;
    constexpr int NT  = TOT / 4;
    const int d   = blockIdx.x;
    const int tid = threadIdx.x;
    const int c4  = tid * 4;
    const int h   = c4 / CPH;

    __shared__ float sadst[H], sce[H], sden[H];
    __shared__ int   ssrc[64];
    __shared__ float sew [64];
    __shared__ float sal [64 * H];

    if (tid < H) { sadst[tid] = adst[d * H + tid]; sce[tid] = ce[tid]; }

    float acc[4] = {0.f, 0.f, 0.f, 0.f};
    float denh = 0.f;                       // valid for tid < H
    const int b0 = rowptr[d], b1 = rowptr[d + 1];

    for (int base = b0; base < b1; base += 64) {
        const int cnt = min(64, b1 - base);
        __syncthreads();
        if (tid < cnt) {
            const int e = csr[base + tid];
            ssrc[tid] = src[e];
            sew[tid]  = ew[e];
        }
        __syncthreads();
        for (int idx = tid; idx < cnt * H; idx += NT) {
            const int i = idx / H, hh = idx - i * H;
            float v = asrc[ssrc[i] * H + hh] + sadst[hh] + sew[i] * sce[hh];
            v = (v > 0.f) ? v : 0.2f * v;
            sal[idx] = __expf(v);
        }
        __syncthreads();
        if (tid < H) {
            for (int i = 0; i < cnt; i++) denh += sal[i * H + tid];
        }
#pragma unroll 4
        for (int i = 0; i < cnt; i++) {
            const uint2 raw = *(const uint2*)&hw[(size_t)ssrc[i] * TOT + c4];
            const float al = sal[i * H + h];
            const __half2* hp = (const __half2*)&raw;
#pragma unroll
            for (int j = 0; j < 2; j++) {
                const float2 f = __half22float2(hp[j]);
                acc[j * 2 + 0] += f.x * al;
                acc[j * 2 + 1] += f.y * al;
            }
        }
    }

    if (tid < H) sden[tid] = denh;
    __syncthreads();
    const float inv = 1.f / (sden[h] + 1e-16f);

#pragma unroll
    for (int j = 0; j < 4; j++) {
        acc[j] = acc[j] * inv + bias[c4 + j];
        if (RELU) acc[j] = fmaxf(acc[j], 0.f);
    }
    if (HALF_OUT) {
        *(__half2*)&outh[(size_t)d * TOT + c4]     = __floats2half2_rn(acc[0], acc[1]);
        *(__half2*)&outh[(size_t)d * TOT + c4 + 2] = __floats2half2_rn(acc[2], acc[3]);
    } else {
        *(float4*)&out[(size_t)d * TOT + c4] = make_float4(acc[0], acc[1], acc[2], acc[3]);
    }
}

// ---------------------------------------------------------------------------
extern "C" void kernel_launch(void* const* d_in, const int* in_sizes, int n_in,
                              void* d_out, int out_size)
{
    (void)in_sizes; (void)n_in; (void)out_size;

    const float* x   = (const float*)d_in[0];
    const int*   ei  = (const int*)  d_in[1];
    const float* ew  = (const float*)d_in[2];
    const float* W1  = (const float*)d_in[3];
    const float* as1 = (const float*)d_in[4];
    const float* ad1 = (const float*)d_in[5];
    const float* We1 = (const float*)d_in[6];
    const float* ae1 = (const float*)d_in[7];
    const float* b1  = (const float*)d_in[8];
    const float* W2  = (const float*)d_in[9];
    const float* as2 = (const float*)d_in[10];
    const float* ad2 = (const float*)d_in[11];
    const float* We2 = (const float*)d_in[12];
    const float* ae2 = (const float*)d_in[13];
    const float* b2  = (const float*)d_in[14];
    const float* W3  = (const float*)d_in[15];
    const float* as3 = (const float*)d_in[16];
    const float* ad3 = (const float*)d_in[17];
    const float* We3 = (const float*)d_in[18];
    const float* ae3 = (const float*)d_in[19];
    const float* b3  = (const float*)d_in[20];
    const int* src = ei;
    const int* dst = ei + EE;
    float* outp = (float*)d_out;

    float *asrc, *adst, *ce;
    __half *hw, *act, *x16, *w1, *w2, *w3;
    int *deg, *rowptr, *cursor, *csr;
    cudaGetSymbolAddress((void**)&hw,     g_hw);
    cudaGetSymbolAddress((void**)&act,    g_act);
    cudaGetSymbolAddress((void**)&x16,    g_x16);
    cudaGetSymbolAddress((void**)&w1,     g_w1);
    cudaGetSymbolAddress((void**)&w2,     g_w2);
    cudaGetSymbolAddress((void**)&w3,     g_w3);
    cudaGetSymbolAddress((void**)&asrc,   g_asrc);
    cudaGetSymbolAddress((void**)&adst,   g_adst);
    cudaGetSymbolAddress((void**)&ce,     g_ce);
    cudaGetSymbolAddress((void**)&deg,    g_deg);
    cudaGetSymbolAddress((void**)&rowptr, g_rowptr);
    cudaGetSymbolAddress((void**)&cursor, g_cursor);
    cudaGetSymbolAddress((void**)&csr,    g_csr);

    cudaFuncSetAttribute(gemm_fp16, cudaFuncAttributeMaxDynamicSharedMemorySize, GSMEM);

    const int MB = (NN + 127) / 128;

    // prep + CSR build; launch #3 is the layer-1 GEMM (ncu captures idx 3)
    transpose_h<<<dim3((NN + 31) / 32, SEQL / 32), dim3(32, 8)>>>(x, x16);      // 0
    conv_w<<<(SEQL * HC + 255) / 256, 256>>>(W1, w1, SEQL * HC);                // 1
    zero_deg<<<(NN + 255) / 256, 256>>>(deg);                                   // 2
    gemm_fp16<<<dim3(HC / 128, MB), 256, GSMEM>>>(x16, w1, hw, NN, SEQL, HC);   // 3
    count_deg<<<(EE + 255) / 256, 256>>>(dst, deg);                             // 4
    scan_rowptr<<<1, 1024>>>(deg, rowptr);                                      // 5
    init_cursor<<<(NN + 255) / 256, 256>>>(rowptr, cursor);
    scatter_csr<<<(EE + 255) / 256, 256>>>(dst, cursor, csr);
    conv_w<<<(HC * HC + 255) / 256, 256>>>(W2, w2, HC * HC);
    conv_w<<<(HC * OUTC + 255) / 256, 256>>>(W3, w3, HC * OUTC);

    // ---------------- Layer 1 ------------------------------------------------
    node_dot<<<(NN * NH * 32 + 255) / 256, 256>>>(hw, as1, ad1, asrc, adst, HIDC, NH);
    ce_kernel<<<1, NH>>>(We1, ae1, ce, HIDC, NH);
    agg_fused<HIDC, NH, true, true><<<NN, HC / 4>>>(rowptr, csr, src, hw, asrc, adst, ew, ce, b1, nullptr, act);

    // ---------------- Layer 2 ------------------------------------------------
    gemm_fp16<<<dim3(HC / 128, MB), 256, GSMEM>>>(act, w2, hw, NN, HC, HC);
    node_dot<<<(NN * NH * 32 + 255) / 256, 256>>>(hw, as2, ad2, asrc, adst, HIDC, NH);
    ce_kernel<<<1, NH>>>(We2, ae2, ce, HIDC, NH);
    agg_fused<HIDC, NH, true, true><<<NN, HC / 4>>>(rowptr, csr, src, hw, asrc, adst, ew, ce, b2, nullptr, act);

    // ---------------- Layer 3 (heads=1, concat=False -> mean = identity) -----
    gemm_fp16<<<dim3(OUTC / 128, MB), 256, GSMEM>>>(act, w3, hw, NN, HC, OUTC);
    node_dot<<<(NN * 32 + 255) / 256, 256>>>(hw, as3, ad3, asrc, adst, OUTC, 1);
    ce_kernel<<<1, 1>>>(We3, ae3, ce, OUTC, 1);
    agg_fused<OUTC, 1, false, false><<<NN, OUTC / 4>>>(rowptr, csr, src, hw, asrc, adst, ew, ce, b3, outp, nullptr);
}

// round 14
// speedup vs baseline: 1.0871x; 1.0871x over previous
#include <cuda_runtime.h>
#include <cuda_fp16.h>
#include <math.h>
#include <stdint.h>

#define NN   10000
#define EE   160000
#define SEQL 96
#define HIDC 128
#define NH   8
#define HC   1024   // NH*HIDC
#define OUTC 768

// ---------------- scratch (device globals; no allocation allowed) ----------
__device__ __half g_hw [NN * HC];    // W-transformed features (fp16 messages)
__device__ __half g_act[NN * HC];    // layer activations (fp16, GEMM A input)
__device__ __half g_x16[NN * SEQL];  // x transposed -> fp16 [NN][SEQ]
__device__ __half g_w1 [SEQL * HC];
__device__ __half g_w2 [HC * HC];
__device__ __half g_w3 [HC * OUTC];
__device__ float g_asrc[NN * NH];
__device__ float g_adst[NN * NH];
__device__ float g_ce  [17];         // ce1[8], ce2[8], ce3[1]
__device__ int   g_deg [NN];
__device__ int   g_rowptr[NN + 1];
__device__ int   g_cursor[NN];
__device__ int   g_csr[EE];

// ======================= fp16 tensor-core GEMM =============================
// C[M,Ncol] = A @ B, fp16 in, fp32 accum, fp16 out; FUSED attention dots:
// asrc[m,h] = sum_c C[m, h*CPH+c]*ws[h,c], adst likewise — computed from the
// fp32 accumulators in the epilogue (no re-read of C).
// HH=8: one head per CTA column-block (direct store). HH=1: atomicAdd.
// CTA tile 128x128, 256 thr (8 warps, 2x4), warp tile 64x32, K-chunk 32.
// Two-stage cp.async pipeline; 2 CTAs/SM.

#define SMSA 40      // A row stride in halves (80B; conflict-free ldmatrix)
#define SMSB 136     // B row stride in halves (272B)
#define OFF_A  0
#define OFF_B  10240                 // 128*40*2
#define BUFSZ  18944                 // + 32*136*2
#define GSMEM  (2 * BUFSZ)           // 37888

__device__ __forceinline__ uint32_t sm32(const void* p) {
    return (uint32_t)__cvta_generic_to_shared(p);
}

__device__ __forceinline__ void cp16(uint32_t dst, const void* src, int bytes) {
    asm volatile("cp.async.cg.shared.global [%0], [%1], 16, %2;"
                 :: "r"(dst), "l"(src), "r"(bytes));
}

__device__ __forceinline__ void cp_commit() {
    asm volatile("cp.async.commit_group;");
}

__device__ __forceinline__ void cp_wait1() {
    asm volatile("cp.async.wait_group 1;");
}

__device__ __forceinline__ void ldm_x4(uint32_t* d, uint32_t addr) {
    asm volatile("ldmatrix.sync.aligned.m8n8.x4.shared.b16 {%0,%1,%2,%3}, [%4];"
                 : "=r"(d[0]), "=r"(d[1]), "=r"(d[2]), "=r"(d[3]) : "r"(addr));
}

__device__ __forceinline__ void ldm_x4_t(uint32_t* d, uint32_t addr) {
    asm volatile("ldmatrix.sync.aligned.m8n8.x4.trans.shared.b16 {%0,%1,%2,%3}, [%4];"
                 : "=r"(d[0]), "=r"(d[1]), "=r"(d[2]), "=r"(d[3]) : "r"(addr));
}

__device__ __forceinline__ void mma_fp16(float* c, const uint32_t* a, const uint32_t* b) {
    asm volatile(
        "mma.sync.aligned.m16n8k16.row.col.f32.f16.f16.f32 "
        "{%0,%1,%2,%3},{%4,%5,%6,%7},{%8,%9},{%0,%1,%2,%3};"
        : "+f"(c[0]), "+f"(c[1]), "+f"(c[2]), "+f"(c[3])
        : "r"(a[0]), "r"(a[1]), "r"(a[2]), "r"(a[3]), "r"(b[0]), "r"(b[1]));
}

template <int HH>
__global__ __launch_bounds__(256, 2) void gemm_fp16(
    const __half* __restrict__ Ag, const __half* __restrict__ Bg,
    __half* __restrict__ C, int M, int K, int Ncol,
    const float* __restrict__ ws, const float* __restrict__ wd,
    float* __restrict__ asrc, float* __restrict__ adst)
{
    extern __shared__ __align__(16) char dyn[];
    const uint32_t smbase = sm32(dyn);
    __shared__ float s_src[128], s_dst[128];

    const int tid  = threadIdx.x;
    const int lane = tid & 31;
    const int w    = tid >> 5;
    const int wr   = w >> 2, wc = w & 3;      // 2x4 warp grid
    const int m0   = blockIdx.y * 128, n0 = blockIdx.x * 128;
    const int r    = lane >> 2, q = lane & 3;

    if (tid < 128) { s_src[tid] = 0.f; s_dst[tid] = 0.f; }

    float acc[4][4][4];
#pragma unroll
    for (int a = 0; a < 4; a++)
#pragma unroll
        for (int b = 0; b < 4; b++)
#pragma unroll
            for (int i = 0; i < 4; i++) acc[a][b][i] = 0.f;

    const int nchunks = K / 32;

    auto issue = [&](int c, int s) {
        if (c < nchunks) {
            const int k0 = c * 32;
            const uint32_t base = smbase + s * BUFSZ;
#pragma unroll
            for (int i = 0; i < 2; i++) {       // A: 128 rows x 64B
                const int idx = i * 256 + tid;
                const int row = idx >> 2, seg = idx & 3;
                const int gm = m0 + row;
                const size_t go = (size_t)gm * K + k0 + seg * 8;
                cp16(base + OFF_A + row * 80 + seg * 16, &Ag[go], (gm < M) ? 16 : 0);
            }
#pragma unroll
            for (int i = 0; i < 2; i++) {       // B: 32 rows x 256B
                const int idx = i * 256 + tid;
                const int row = idx >> 4, seg = idx & 15;
                const size_t go = (size_t)(k0 + row) * Ncol + n0 + seg * 8;
                cp16(base + OFF_B + row * 272 + seg * 16, &Bg[go], 16);
            }
        }
        cp_commit();
    };

    uint32_t aaddr[4];
#pragma unroll
    for (int mt = 0; mt < 4; mt++)
        aaddr[mt] = smbase + OFF_A + (wr * 64 + mt * 16 + (lane & 15)) * 80 + (lane >> 4) * 16;
    uint32_t baddr[2];
#pragma unroll
    for (int g = 0; g < 2; g++)
        baddr[g] = smbase + OFF_B + (lane & 15) * 272 + (wc * 32 + g * 16 + 8 * (lane >> 4)) * 2;

    auto pass = [&](uint32_t boff, int kb) {
        uint32_t af[4][4], bf[2][4];
#pragma unroll
        for (int mt = 0; mt < 4; mt++) ldm_x4(af[mt], aaddr[mt] + boff + kb * 2);
#pragma unroll
        for (int g = 0; g < 2; g++) ldm_x4_t(bf[g], baddr[g] + boff + kb * 272);
#pragma unroll
        for (int mt = 0; mt < 4; mt++)
#pragma unroll
            for (int nt = 0; nt < 4; nt++)
                mma_fp16(acc[mt][nt], af[mt], &bf[nt >> 1][(nt & 1) * 2]);
    };

    issue(0, 0);
    issue(1, 1);
    for (int c = 0; c < nchunks; c++) {
        const uint32_t boff = (c & 1) * BUFSZ;
        cp_wait1();
        __syncthreads();
        pass(boff, 0);
        pass(boff, 16);
        __syncthreads();
        issue(c + 2, c & 1);
    }

    // ---- epilogue 1: store C as fp16 ----
#pragma unroll
    for (int mt = 0; mt < 4; mt++) {
        const int r0 = m0 + wr * 64 + mt * 16 + r;
        const int r1 = r0 + 8;
#pragma unroll
        for (int nt = 0; nt < 4; nt++) {
            const int col = n0 + wc * 32 + nt * 8 + 2 * q;
            if (r0 < M)
                *(__half2*)&C[(size_t)r0 * Ncol + col] =
                    __floats2half2_rn(acc[mt][nt][0], acc[mt][nt][1]);
            if (r1 < M)
                *(__half2*)&C[(size_t)r1 * Ncol + col] =
                    __floats2half2_rn(acc[mt][nt][2], acc[mt][nt][3]);
        }
    }

    // ---- epilogue 2: fused attention dots ----
    const float* wsp = ws + ((HH == NH) ? (size_t)blockIdx.x * 128 : (size_t)n0);
    const float* wdp = wd + ((HH == NH) ? (size_t)blockIdx.x * 128 : (size_t)n0);
#pragma unroll
    for (int mt = 0; mt < 4; mt++) {
        float p0s = 0.f, p1s = 0.f, p0d = 0.f, p1d = 0.f;
#pragma unroll
        for (int nt = 0; nt < 4; nt++) {
            const int col = wc * 32 + nt * 8 + 2 * q;
            const float w0 = wsp[col], w1 = wsp[col + 1];
            const float d0 = wdp[col], d1 = wdp[col + 1];
            p0s += acc[mt][nt][0] * w0 + acc[mt][nt][1] * w1;
            p1s += acc[mt][nt][2] * w0 + acc[mt][nt][3] * w1;
            p0d += acc[mt][nt][0] * d0 + acc[mt][nt][1] * d1;
            p1d += acc[mt][nt][2] * d0 + acc[mt][nt][3] * d1;
        }
#pragma unroll
        for (int o = 1; o < 4; o <<= 1) {       // reduce over q (low 2 lane bits)
            p0s += __shfl_xor_sync(0xffffffffu, p0s, o);
            p1s += __shfl_xor_sync(0xffffffffu, p1s, o);
            p0d += __shfl_xor_sync(0xffffffffu, p0d, o);
            p1d += __shfl_xor_sync(0xffffffffu, p1d, o);
        }
        if (q == 0) {
            const int row = wr * 64 + mt * 16 + r;
            atomicAdd(&s_src[row], p0s);
            atomicAdd(&s_src[row + 8], p1s);
            atomicAdd(&s_dst[row], p0d);
            atomicAdd(&s_dst[row + 8], p1d);
        }
    }
    __syncthreads();
    if (tid < 128) {
        const int gm = m0 + tid;
        if (gm < M) {
            if (HH == NH) {
                asrc[gm * NH + blockIdx.x] = s_src[tid];
                adst[gm * NH + blockIdx.x] = s_dst[tid];
            } else {
                atomicAdd(&asrc[gm], s_src[tid]);
                atomicAdd(&adst[gm], s_dst[tid]);
            }
        }
    }
}

// ---------------- prep: elementwise fp32 -> fp16 --------------------------
__global__ void conv_w(const float* __restrict__ w, __half* __restrict__ wh, int n)
{
    const int i = blockIdx.x * blockDim.x + threadIdx.x;
    if (i < n) wh[i] = __float2half_rn(w[i]);
}

// ---------------- prep: transpose x [SEQ][NN] -> fp16 [NN][SEQ] -----------
__global__ void transpose_h(const float* __restrict__ x, __half* __restrict__ xh)
{
    __shared__ float sm[32][33];
    const int m0 = blockIdx.x * 32, k0 = blockIdx.y * 32;
    const int tx = threadIdx.x, ty = threadIdx.y;   // 32x8
#pragma unroll
    for (int j = 0; j < 4; j++) {
        const int k = k0 + ty + j * 8, m = m0 + tx;
        sm[ty + j * 8][tx] = (m < NN) ? x[(size_t)k * NN + m] : 0.f;
    }
    __syncthreads();
#pragma unroll
    for (int j = 0; j < 4; j++) {
        const int m = m0 + ty + j * 8, k = k0 + tx;
        if (m < NN) xh[(size_t)m * SEQL + k] = __float2half_rn(sm[tx][ty + j * 8]);
    }
}

// ---- all three edge-coefficient dots in one launch -----------------------
__global__ void ce_all(const float* __restrict__ We1, const float* __restrict__ ae1,
                       const float* __restrict__ We2, const float* __restrict__ ae2,
                       const float* __restrict__ We3, const float* __restrict__ ae3,
                       float* __restrict__ ce)
{
    const int t = threadIdx.x;
    if (t < 8) {
        float s = 0.f;
        for (int c = 0; c < HIDC; c++) s += We1[t * HIDC + c] * ae1[t * HIDC + c];
        ce[t] = s;
    } else if (t < 16) {
        const int h = t - 8;
        float s = 0.f;
        for (int c = 0; c < HIDC; c++) s += We2[h * HIDC + c] * ae2[h * HIDC + c];
        ce[8 + h] = s;
    } else if (t == 16) {
        float s = 0.f;
        for (int c = 0; c < OUTC; c++) s += We3[c] * ae3[c];
        ce[16] = s;
    }
}

__global__ void zero_ad(float* __restrict__ a, float* __restrict__ b)
{
    const int i = blockIdx.x * blockDim.x + threadIdx.x;
    if (i < NN) { a[i] = 0.f; b[i] = 0.f; }
}

// ======================= CSR build (once per launch) =======================
__global__ void zero_deg(int* __restrict__ deg)
{
    const int i = blockIdx.x * blockDim.x + threadIdx.x;
    if (i < NN) deg[i] = 0;
}

__global__ void count_deg(const int* __restrict__ dst, int* __restrict__ deg)
{
    const int e = blockIdx.x * blockDim.x + threadIdx.x;
    if (e < EE) atomicAdd(&deg[dst[e]], 1);
}

__global__ void scan_rowptr(const int* __restrict__ deg, int* __restrict__ rowptr)
{
    __shared__ int ssum[1024];
    const int t = threadIdx.x;
    const int CHK = (NN + 1023) / 1024;
    const int base = t * CHK;
    int s = 0;
    for (int i = 0; i < CHK; i++) {
        const int idx = base + i;
        if (idx < NN) s += deg[idx];
    }
    ssum[t] = s;
    __syncthreads();
    for (int off = 1; off < 1024; off <<= 1) {
        int v = (t >= off) ? ssum[t - off] : 0;
        __syncthreads();
        ssum[t] += v;
        __syncthreads();
    }
    int run = ssum[t] - s;
    for (int i = 0; i < CHK; i++) {
        const int idx = base + i;
        if (idx < NN) { rowptr[idx] = run; run += deg[idx]; }
    }
    if (t == 0) rowptr[NN] = EE;
}

__global__ void init_cursor(const int* __restrict__ rowptr, int* __restrict__ cursor)
{
    const int i = blockIdx.x * blockDim.x + threadIdx.x;
    if (i < NN) cursor[i] = rowptr[i];
}

__global__ void scatter_csr(const int* __restrict__ dst, int* __restrict__ cursor,
                            int* __restrict__ csr)
{
    const int e = blockIdx.x * blockDim.x + threadIdx.x;
    if (e >= EE) return;
    const int pos = atomicAdd(&cursor[dst[e]], 1);
    csr[pos] = e;
}

// == FUSED softmax + CSR aggregation: one block per node, 8 ch/thread =======
template <int CPH, int H, bool RELU, bool HALF_OUT>
__global__ __launch_bounds__(128) void agg_fused(
                        const int* __restrict__ rowptr, const int* __restrict__ csr,
                        const int* __restrict__ src, const __half* __restrict__ hw,
                        const float* __restrict__ asrc, const float* __restrict__ adst,
                        const float* __restrict__ ew, const float* __restrict__ ce,
                        const float* __restrict__ bias, float* __restrict__ out,
                        __half* __restrict__ outh)
{
    constexpr int TOT = CPH * H;
    constexpr int NT  = TOT / 8;
    const int d   = blockIdx.x;
    const int tid = threadIdx.x;
    const int c8  = tid * 8;
    const int h   = c8 / CPH;

    __shared__ float sadst[H], sce[H], sden[H];
    __shared__ int   ssrc[64];
    __shared__ float sew [64];
    __shared__ float sal [64 * H];

    if (tid < H) { sadst[tid] = adst[d * H + tid]; sce[tid] = ce[tid]; }

    float acc[8] = {0.f, 0.f, 0.f, 0.f, 0.f, 0.f, 0.f, 0.f};
    float denh = 0.f;                       // valid for tid < H
    const int b0 = rowptr[d], b1 = rowptr[d + 1];

    for (int base = b0; base < b1; base += 64) {
        const int cnt = min(64, b1 - base);
        __syncthreads();
        if (tid < cnt) {
            const int e = csr[base + tid];
            ssrc[tid] = src[e];
            sew[tid]  = ew[e];
        }
        __syncthreads();
        for (int idx = tid; idx < cnt * H; idx += NT) {
            const int i = idx / H, hh = idx - i * H;
            float v = asrc[ssrc[i] * H + hh] + sadst[hh] + sew[i] * sce[hh];
            v = (v > 0.f) ? v : 0.2f * v;
            sal[idx] = __expf(v);
        }
        __syncthreads();
        if (tid < H) {
            for (int i = 0; i < cnt; i++) denh += sal[i * H + tid];
        }
#pragma unroll 2
        for (int i = 0; i < cnt; i++) {
            const uint4 raw = *(const uint4*)&hw[(size_t)ssrc[i] * TOT + c8];
            const float al = sal[i * H + h];
            const __half2* hp = (const __half2*)&raw;
#pragma unroll
            for (int j = 0; j < 4; j++) {
                const float2 f = __half22float2(hp[j]);
                acc[j * 2 + 0] += f.x * al;
                acc[j * 2 + 1] += f.y * al;
            }
        }
    }

    if (tid < H) sden[tid] = denh;
    __syncthreads();
    const float inv = 1.f / (sden[h] + 1e-16f);

#pragma unroll
    for (int j = 0; j < 8; j++) {
        acc[j] = acc[j] * inv + bias[c8 + j];
        if (RELU) acc[j] = fmaxf(acc[j], 0.f);
    }
    if (HALF_OUT) {
#pragma unroll
        for (int j = 0; j < 4; j++)
            *(__half2*)&outh[(size_t)d * TOT + c8 + j * 2] =
                __floats2half2_rn(acc[j * 2], acc[j * 2 + 1]);
    } else {
        *(float4*)&out[(size_t)d * TOT + c8]     = make_float4(acc[0], acc[1], acc[2], acc[3]);
        *(float4*)&out[(size_t)d * TOT + c8 + 4] = make_float4(acc[4], acc[5], acc[6], acc[7]);
    }
}

// ---------------------------------------------------------------------------
extern "C" void kernel_launch(void* const* d_in, const int* in_sizes, int n_in,
                              void* d_out, int out_size)
{
    (void)in_sizes; (void)n_in; (void)out_size;

    const float* x   = (const float*)d_in[0];
    const int*   ei  = (const int*)  d_in[1];
    const float* ew  = (const float*)d_in[2];
    const float* W1  = (const float*)d_in[3];
    const float* as1 = (const float*)d_in[4];
    const float* ad1 = (const float*)d_in[5];
    const float* We1 = (const float*)d_in[6];
    const float* ae1 = (const float*)d_in[7];
    const float* b1  = (const float*)d_in[8];
    const float* W2  = (const float*)d_in[9];
    const float* as2 = (const float*)d_in[10];
    const float* ad2 = (const float*)d_in[11];
    const float* We2 = (const float*)d_in[12];
    const float* ae2 = (const float*)d_in[13];
    const float* b2  = (const float*)d_in[14];
    const float* W3  = (const float*)d_in[15];
    const float* as3 = (const float*)d_in[16];
    const float* ad3 = (const float*)d_in[17];
    const float* We3 = (const float*)d_in[18];
    const float* ae3 = (const float*)d_in[19];
    const float* b3  = (const float*)d_in[20];
    const int* src = ei;
    const int* dst = ei + EE;
    float* outp = (float*)d_out;

    float *asrc, *adst, *ce;
    __half *hw, *act, *x16, *w1, *w2, *w3;
    int *deg, *rowptr, *cursor, *csr;
    cudaGetSymbolAddress((void**)&hw,     g_hw);
    cudaGetSymbolAddress((void**)&act,    g_act);
    cudaGetSymbolAddress((void**)&x16,    g_x16);
    cudaGetSymbolAddress((void**)&w1,     g_w1);
    cudaGetSymbolAddress((void**)&w2,     g_w2);
    cudaGetSymbolAddress((void**)&w3,     g_w3);
    cudaGetSymbolAddress((void**)&asrc,   g_asrc);
    cudaGetSymbolAddress((void**)&adst,   g_adst);
    cudaGetSymbolAddress((void**)&ce,     g_ce);
    cudaGetSymbolAddress((void**)&deg,    g_deg);
    cudaGetSymbolAddress((void**)&rowptr, g_rowptr);
    cudaGetSymbolAddress((void**)&cursor, g_cursor);
    cudaGetSymbolAddress((void**)&csr,    g_csr);

    cudaFuncSetAttribute(gemm_fp16<NH>, cudaFuncAttributeMaxDynamicSharedMemorySize, GSMEM);
    cudaFuncSetAttribute(gemm_fp16<1>,  cudaFuncAttributeMaxDynamicSharedMemorySize, GSMEM);

    const int MB = (NN + 127) / 128;

    // prep + CSR build; launch #3 is the layer-1 GEMM (ncu captures idx 3)
    transpose_h<<<dim3((NN + 31) / 32, SEQL / 32), dim3(32, 8)>>>(x, x16);      // 0
    conv_w<<<(SEQL * HC + 255) / 256, 256>>>(W1, w1, SEQL * HC);                // 1
    zero_deg<<<(NN + 255) / 256, 256>>>(deg);                                   // 2
    gemm_fp16<NH><<<dim3(HC / 128, MB), 256, GSMEM>>>(x16, w1, hw, NN, SEQL, HC,
                                                      as1, ad1, asrc, adst);    // 3
    count_deg<<<(EE + 255) / 256, 256>>>(dst, deg);                             // 4
    scan_rowptr<<<1, 1024>>>(deg, rowptr);                                      // 5
    init_cursor<<<(NN + 255) / 256, 256>>>(rowptr, cursor);
    scatter_csr<<<(EE + 255) / 256, 256>>>(dst, cursor, csr);
    conv_w<<<(HC * HC + 255) / 256, 256>>>(W2, w2, HC * HC);
    conv_w<<<(HC * OUTC + 255) / 256, 256>>>(W3, w3, HC * OUTC);
    ce_all<<<1, 32>>>(We1, ae1, We2, ae2, We3, ae3, ce);

    // ---------------- Layer 1 ------------------------------------------------
    agg_fused<HIDC, NH, true, true><<<NN, HC / 8>>>(rowptr, csr, src, hw, asrc, adst, ew, ce, b1, nullptr, act);

    // ---------------- Layer 2 ------------------------------------------------
    gemm_fp16<NH><<<dim3(HC / 128, MB), 256, GSMEM>>>(act, w2, hw, NN, HC, HC,
                                                      as2, ad2, asrc, adst);
    agg_fused<HIDC, NH, true, true><<<NN, HC / 8>>>(rowptr, csr, src, hw, asrc, adst, ew, ce + 8, b2, nullptr, act);

    // ---------------- Layer 3 (heads=1, concat=False -> mean = identity) -----
    zero_ad<<<(NN + 255) / 256, 256>>>(asrc, adst);
    gemm_fp16<1><<<dim3(OUTC / 128, MB), 256, GSMEM>>>(act, w3, hw, NN, HC, OUTC,
                                                       as3, ad3, asrc, adst);
    agg_fused<OUTC, 1, false, false><<<NN, OUTC / 8>>>(rowptr, csr, src, hw, asrc, adst, ew, ce + 16, b3, outp, nullptr);
}

// round 16
// speedup vs baseline: 1.0896x; 1.0023x over previous
#include <cuda_runtime.h>
#include <cuda_fp16.h>
#include <math.h>
#include <stdint.h>

#define NN   10000
#define EE   160000
#define SEQL 96
#define HIDC 128
#define NH   8
#define HC   1024   // NH*HIDC
#define OUTC 768

// ---------------- scratch (device globals; no allocation allowed) ----------
__device__ __half g_hw [NN * HC];    // W-transformed features (fp16 messages)
__device__ __half g_act[NN * HC];    // layer activations (fp16, GEMM A input)
__device__ __half g_x16[NN * SEQL];  // x transposed -> fp16 [NN][SEQ]
__device__ __half g_w1 [SEQL * HC];
__device__ __half g_w2 [HC * HC];
__device__ __half g_w3 [HC * OUTC];
__device__ float g_asrc[NN * NH];
__device__ float g_adst[NN * NH];
__device__ float g_ce  [17];         // ce1[8], ce2[8], ce3[1]
__device__ int   g_deg [NN];
__device__ int   g_rowptr[NN + 1];
__device__ int   g_cursor[NN];
__device__ int   g_csr[EE];

// ======================= fp16 tensor-core GEMM =============================
// C[M,Ncol] = A @ B, fp16 in, fp32 accum, fp16 out; FUSED attention dots
// (asrc/adst from fp32 accumulators; ws/wd staged through smem).
// HH=8: one head per CTA column-block (direct store). HH=1: atomicAdd.
// CTA tile 128x128, 256 thr (8 warps, 2x4), warp tile 64x32, K-chunk 32.
// Two-stage cp.async pipeline; 2 CTAs/SM.

#define SMSA 40      // A row stride in halves (80B; conflict-free ldmatrix)
#define SMSB 136     // B row stride in halves (272B)
#define OFF_A  0
#define OFF_B  10240                 // 128*40*2
#define BUFSZ  18944                 // + 32*136*2
#define GSMEM  (2 * BUFSZ)           // 37888

__device__ __forceinline__ uint32_t sm32(const void* p) {
    return (uint32_t)__cvta_generic_to_shared(p);
}

__device__ __forceinline__ void cp16(uint32_t dst, const void* src, int bytes) {
    asm volatile("cp.async.cg.shared.global [%0], [%1], 16, %2;"
                 :: "r"(dst), "l"(src), "r"(bytes));
}

__device__ __forceinline__ void cp_commit() {
    asm volatile("cp.async.commit_group;");
}

__device__ __forceinline__ void cp_wait1() {
    asm volatile("cp.async.wait_group 1;");
}

__device__ __forceinline__ void ldm_x4(uint32_t* d, uint32_t addr) {
    asm volatile("ldmatrix.sync.aligned.m8n8.x4.shared.b16 {%0,%1,%2,%3}, [%4];"
                 : "=r"(d[0]), "=r"(d[1]), "=r"(d[2]), "=r"(d[3]) : "r"(addr));
}

__device__ __forceinline__ void ldm_x4_t(uint32_t* d, uint32_t addr) {
    asm volatile("ldmatrix.sync.aligned.m8n8.x4.trans.shared.b16 {%0,%1,%2,%3}, [%4];"
                 : "=r"(d[0]), "=r"(d[1]), "=r"(d[2]), "=r"(d[3]) : "r"(addr));
}

__device__ __forceinline__ void mma_fp16(float* c, const uint32_t* a, const uint32_t* b) {
    asm volatile(
        "mma.sync.aligned.m16n8k16.row.col.f32.f16.f16.f32 "
        "{%0,%1,%2,%3},{%4,%5,%6,%7},{%8,%9},{%0,%1,%2,%3};"
        : "+f"(c[0]), "+f"(c[1]), "+f"(c[2]), "+f"(c[3])
        : "r"(a[0]), "r"(a[1]), "r"(a[2]), "r"(a[3]), "r"(b[0]), "r"(b[1]));
}

template <int HH>
__global__ __launch_bounds__(256, 2) void gemm_fp16(
    const __half* __restrict__ Ag, const __half* __restrict__ Bg,
    __half* __restrict__ C, int M, int K, int Ncol,
    const float* __restrict__ ws, const float* __restrict__ wd,
    float* __restrict__ asrc, float* __restrict__ adst)
{
    extern __shared__ __align__(16) char dyn[];
    const uint32_t smbase = sm32(dyn);
    __shared__ float s_src[128], s_dst[128];

    const int tid  = threadIdx.x;
    const int lane = tid & 31;
    const int w    = tid >> 5;
    const int wr   = w >> 2, wc = w & 3;      // 2x4 warp grid
    const int m0   = blockIdx.y * 128, n0 = blockIdx.x * 128;
    const int r    = lane >> 2, q = lane & 3;

    if (tid < 128) { s_src[tid] = 0.f; s_dst[tid] = 0.f; }

    float acc[4][4][4];
#pragma unroll
    for (int a = 0; a < 4; a++)
#pragma unroll
        for (int b = 0; b < 4; b++)
#pragma unroll
            for (int i = 0; i < 4; i++) acc[a][b][i] = 0.f;

    const int nchunks = K / 32;

    auto issue = [&](int c, int s) {
        if (c < nchunks) {
            const int k0 = c * 32;
            const uint32_t base = smbase + s * BUFSZ;
#pragma unroll
            for (int i = 0; i < 2; i++) {       // A: 128 rows x 64B
                const int idx = i * 256 + tid;
                const int row = idx >> 2, seg = idx & 3;
                const int gm = m0 + row;
                const size_t go = (size_t)gm * K + k0 + seg * 8;
                cp16(base + OFF_A + row * 80 + seg * 16, &Ag[go], (gm < M) ? 16 : 0);
            }
#pragma unroll
            for (int i = 0; i < 2; i++) {       // B: 32 rows x 256B
                const int idx = i * 256 + tid;
                const int row = idx >> 4, seg = idx & 15;
                const size_t go = (size_t)(k0 + row) * Ncol + n0 + seg * 8;
                cp16(base + OFF_B + row * 272 + seg * 16, &Bg[go], 16);
            }
        }
        cp_commit();
    };

    uint32_t aaddr[4];
#pragma unroll
    for (int mt = 0; mt < 4; mt++)
        aaddr[mt] = smbase + OFF_A + (wr * 64 + mt * 16 + (lane & 15)) * 80 + (lane >> 4) * 16;
    uint32_t baddr[2];
#pragma unroll
    for (int g = 0; g < 2; g++)
        baddr[g] = smbase + OFF_B + (lane & 15) * 272 + (wc * 32 + g * 16 + 8 * (lane >> 4)) * 2;

    auto pass = [&](uint32_t boff, int kb) {
        uint32_t af[4][4], bf[2][4];
#pragma unroll
        for (int mt = 0; mt < 4; mt++) ldm_x4(af[mt], aaddr[mt] + boff + kb * 2);
#pragma unroll
        for (int g = 0; g < 2; g++) ldm_x4_t(bf[g], baddr[g] + boff + kb * 272);
#pragma unroll
        for (int mt = 0; mt < 4; mt++)
#pragma unroll
            for (int nt = 0; nt < 4; nt++)
                mma_fp16(acc[mt][nt], af[mt], &bf[nt >> 1][(nt & 1) * 2]);
    };

    issue(0, 0);
    issue(1, 1);
    for (int c = 0; c < nchunks; c++) {
        const uint32_t boff = (c & 1) * BUFSZ;
        cp_wait1();
        __syncthreads();
        pass(boff, 0);
        pass(boff, 16);
        __syncthreads();
        issue(c + 2, c & 1);
    }

    // ---- epilogue 1: store C as fp16 ----
#pragma unroll
    for (int mt = 0; mt < 4; mt++) {
        const int r0 = m0 + wr * 64 + mt * 16 + r;
        const int r1 = r0 + 8;
#pragma unroll
        for (int nt = 0; nt < 4; nt++) {
            const int col = n0 + wc * 32 + nt * 8 + 2 * q;
            if (r0 < M)
                *(__half2*)&C[(size_t)r0 * Ncol + col] =
                    __floats2half2_rn(acc[mt][nt][0], acc[mt][nt][1]);
            if (r1 < M)
                *(__half2*)&C[(size_t)r1 * Ncol + col] =
                    __floats2half2_rn(acc[mt][nt][2], acc[mt][nt][3]);
        }
    }

    // ---- epilogue 2: fused attention dots (ws/wd staged through smem) ----
    // mainloop smem is dead now; reuse its first 1KB for the weight slices.
    const float* wsp = ws + ((HH == NH) ? (size_t)blockIdx.x * 128 : (size_t)n0);
    const float* wdp = wd + ((HH == NH) ? (size_t)blockIdx.x * 128 : (size_t)n0);
    float* const sws = (float*)dyn;         // [128]
    float* const swd = sws + 128;           // [128]
    __syncthreads();                        // all warps past mainloop smem use
    if (tid < 128) sws[tid] = wsp[tid];
    else           swd[tid - 128] = wdp[tid - 128];
    __syncthreads();

#pragma unroll
    for (int mt = 0; mt < 4; mt++) {
        float p0s = 0.f, p1s = 0.f, p0d = 0.f, p1d = 0.f;
#pragma unroll
        for (int nt = 0; nt < 4; nt++) {
            const int col = wc * 32 + nt * 8 + 2 * q;
            const float w0 = sws[col], w1 = sws[col + 1];
            const float d0 = swd[col], d1 = swd[col + 1];
            p0s += acc[mt][nt][0] * w0 + acc[mt][nt][1] * w1;
            p1s += acc[mt][nt][2] * w0 + acc[mt][nt][3] * w1;
            p0d += acc[mt][nt][0] * d0 + acc[mt][nt][1] * d1;
            p1d += acc[mt][nt][2] * d0 + acc[mt][nt][3] * d1;
        }
#pragma unroll
        for (int o = 1; o < 4; o <<= 1) {       // reduce over q (low 2 lane bits)
            p0s += __shfl_xor_sync(0xffffffffu, p0s, o);
            p1s += __shfl_xor_sync(0xffffffffu, p1s, o);
            p0d += __shfl_xor_sync(0xffffffffu, p0d, o);
            p1d += __shfl_xor_sync(0xffffffffu, p1d, o);
        }
        if (q == 0) {
            const int row = wr * 64 + mt * 16 + r;
            atomicAdd(&s_src[row], p0s);
            atomicAdd(&s_src[row + 8], p1s);
            atomicAdd(&s_dst[row], p0d);
            atomicAdd(&s_dst[row + 8], p1d);
        }
    }
    __syncthreads();
    if (tid < 128) {
        const int gm = m0 + tid;
        if (gm < M) {
            if (HH == NH) {
                asrc[gm * NH + blockIdx.x] = s_src[tid];
                adst[gm * NH + blockIdx.x] = s_dst[tid];
            } else {
                atomicAdd(&asrc[gm], s_src[tid]);
                atomicAdd(&adst[gm], s_dst[tid]);
            }
        }
    }
}

// ---------------- prep: elementwise fp32 -> fp16 --------------------------
__global__ void conv_w(const float* __restrict__ w, __half* __restrict__ wh, int n)
{
    const int i = blockIdx.x * blockDim.x + threadIdx.x;
    if (i < n) wh[i] = __float2half_rn(w[i]);
}

// ---------------- prep: transpose x [SEQ][NN] -> fp16 [NN][SEQ] -----------
__global__ void transpose_h(const float* __restrict__ x, __half* __restrict__ xh)
{
    __shared__ float sm[32][33];
    const int m0 = blockIdx.x * 32, k0 = blockIdx.y * 32;
    const int tx = threadIdx.x, ty = threadIdx.y;   // 32x8
#pragma unroll
    for (int j = 0; j < 4; j++) {
        const int k = k0 + ty + j * 8, m = m0 + tx;
        sm[ty + j * 8][tx] = (m < NN) ? x[(size_t)k * NN + m] : 0.f;
    }
    __syncthreads();
#pragma unroll
    for (int j = 0; j < 4; j++) {
        const int m = m0 + ty + j * 8, k = k0 + tx;
        if (m < NN) xh[(size_t)m * SEQL + k] = __float2half_rn(sm[tx][ty + j * 8]);
    }
}

// ---- all three edge-coefficient dots in one launch -----------------------
__global__ void ce_all(const float* __restrict__ We1, const float* __restrict__ ae1,
                       const float* __restrict__ We2, const float* __restrict__ ae2,
                       const float* __restrict__ We3, const float* __restrict__ ae3,
                       float* __restrict__ ce)
{
    const int t = threadIdx.x;
    if (t < 8) {
        float s = 0.f;
        for (int c = 0; c < HIDC; c++) s += We1[t * HIDC + c] * ae1[t * HIDC + c];
        ce[t] = s;
    } else if (t < 16) {
        const int h = t - 8;
        float s = 0.f;
        for (int c = 0; c < HIDC; c++) s += We2[h * HIDC + c] * ae2[h * HIDC + c];
        ce[8 + h] = s;
    } else if (t == 16) {
        float s = 0.f;
        for (int c = 0; c < OUTC; c++) s += We3[c] * ae3[c];
        ce[16] = s;
    }
}

__global__ void zero_ad(float* __restrict__ a, float* __restrict__ b)
{
    const int i = blockIdx.x * blockDim.x + threadIdx.x;
    if (i < NN) { a[i] = 0.f; b[i] = 0.f; }
}

// ======================= CSR build (once per launch) =======================
__global__ void zero_deg(int* __restrict__ deg)
{
    const int i = blockIdx.x * blockDim.x + threadIdx.x;
    if (i < NN) deg[i] = 0;
}

__global__ void count_deg(const int* __restrict__ dst, int* __restrict__ deg)
{
    const int e = blockIdx.x * blockDim.x + threadIdx.x;
    if (e < EE) atomicAdd(&deg[dst[e]], 1);
}

__global__ void scan_rowptr(const int* __restrict__ deg, int* __restrict__ rowptr)
{
    __shared__ int ssum[1024];
    const int t = threadIdx.x;
    const int CHK = (NN + 1023) / 1024;
    const int base = t * CHK;
    int s = 0;
    for (int i = 0; i < CHK; i++) {
        const int idx = base + i;
        if (idx < NN) s += deg[idx];
    }
    ssum[t] = s;
    __syncthreads();
    for (int off = 1; off < 1024; off <<= 1) {
        int v = (t >= off) ? ssum[t - off] : 0;
        __syncthreads();
        ssum[t] += v;
        __syncthreads();
    }
    int run = ssum[t] - s;
    for (int i = 0; i < CHK; i++) {
        const int idx = base + i;
        if (idx < NN) { rowptr[idx] = run; run += deg[idx]; }
    }
    if (t == 0) rowptr[NN] = EE;
}

__global__ void init_cursor(const int* __restrict__ rowptr, int* __restrict__ cursor)
{
    const int i = blockIdx.x * blockDim.x + threadIdx.x;
    if (i < NN) cursor[i] = rowptr[i];
}

__global__ void scatter_csr(const int* __restrict__ dst, int* __restrict__ cursor,
                            int* __restrict__ csr)
{
    const int e = blockIdx.x * blockDim.x + threadIdx.x;
    if (e >= EE) return;
    const int pos = atomicAdd(&cursor[dst[e]], 1);
    csr[pos] = e;
}

// == FUSED softmax + CSR aggregation: one block per node, 8 ch/thread =======
template <int CPH, int H, bool RELU, bool HALF_OUT>
__global__ __launch_bounds__(128) void agg_fused(
                        const int* __restrict__ rowptr, const int* __restrict__ csr,
                        const int* __restrict__ src, const __half* __restrict__ hw,
                        const float* __restrict__ asrc, const float* __restrict__ adst,
                        const float* __restrict__ ew, const float* __restrict__ ce,
                        const float* __restrict__ bias, float* __restrict__ out,
                        __half* __restrict__ outh)
{
    constexpr int TOT = CPH * H;
    constexpr int NT  = TOT / 8;
    const int d   = blockIdx.x;
    const int tid = threadIdx.x;
    const int c8  = tid * 8;
    const int h   = c8 / CPH;

    __shared__ float sadst[H], sce[H], sden[H];
    __shared__ int   ssrc[64];
    __shared__ float sew [64];
    __shared__ float sal [64 * H];

    if (tid < H) { sadst[tid] = adst[d * H + tid]; sce[tid] = ce[tid]; }

    float acc[8] = {0.f, 0.f, 0.f, 0.f, 0.f, 0.f, 0.f, 0.f};
    float denh = 0.f;                       // valid for tid < H
    const int b0 = rowptr[d], b1 = rowptr[d + 1];

    for (int base = b0; base < b1; base += 64) {
        const int cnt = min(64, b1 - base);
        __syncthreads();
        if (tid < cnt) {
            const int e = csr[base + tid];
            ssrc[tid] = src[e];
            sew[tid]  = ew[e];
        }
        __syncthreads();
        for (int idx = tid; idx < cnt * H; idx += NT) {
            const int i = idx / H, hh = idx - i * H;
            float v = asrc[ssrc[i] * H + hh] + sadst[hh] + sew[i] * sce[hh];
            v = (v > 0.f) ? v : 0.2f * v;
            sal[idx] = __expf(v);
        }
        __syncthreads();
        if (tid < H) {
            for (int i = 0; i < cnt; i++) denh += sal[i * H + tid];
        }
#pragma unroll 4
        for (int i = 0; i < cnt; i++) {
            const uint4 raw = *(const uint4*)&hw[(size_t)ssrc[i] * TOT + c8];
            const float al = sal[i * H + h];
            const __half2* hp = (const __half2*)&raw;
#pragma unroll
            for (int j = 0; j < 4; j++) {
                const float2 f = __half22float2(hp[j]);
                acc[j * 2 + 0] += f.x * al;
                acc[j * 2 + 1] += f.y * al;
            }
        }
    }

    if (tid < H) sden[tid] = denh;
    __syncthreads();
    const float inv = 1.f / (sden[h] + 1e-16f);

#pragma unroll
    for (int j = 0; j < 8; j++) {
        acc[j] = acc[j] * inv + bias[c8 + j];
        if (RELU) acc[j] = fmaxf(acc[j], 0.f);
    }
    if (HALF_OUT) {
#pragma unroll
        for (int j = 0; j < 4; j++)
            *(__half2*)&outh[(size_t)d * TOT + c8 + j * 2] =
                __floats2half2_rn(acc[j * 2], acc[j * 2 + 1]);
    } else {
        *(float4*)&out[(size_t)d * TOT + c8]     = make_float4(acc[0], acc[1], acc[2], acc[3]);
        *(float4*)&out[(size_t)d * TOT + c8 + 4] = make_float4(acc[4], acc[5], acc[6], acc[7]);
    }
}

// ---------------------------------------------------------------------------
extern "C" void kernel_launch(void* const* d_in, const int* in_sizes, int n_in,
                              void* d_out, int out_size)
{
    (void)in_sizes; (void)n_in; (void)out_size;

    const float* x   = (const float*)d_in[0];
    const int*   ei  = (const int*)  d_in[1];
    const float* ew  = (const float*)d_in[2];
    const float* W1  = (const float*)d_in[3];
    const float* as1 = (const float*)d_in[4];
    const float* ad1 = (const float*)d_in[5];
    const float* We1 = (const float*)d_in[6];
    const float* ae1 = (const float*)d_in[7];
    const float* b1  = (const float*)d_in[8];
    const float* W2  = (const float*)d_in[9];
    const float* as2 = (const float*)d_in[10];
    const float* ad2 = (const float*)d_in[11];
    const float* We2 = (const float*)d_in[12];
    const float* ae2 = (const float*)d_in[13];
    const float* b2  = (const float*)d_in[14];
    const float* W3  = (const float*)d_in[15];
    const float* as3 = (const float*)d_in[16];
    const float* ad3 = (const float*)d_in[17];
    const float* We3 = (const float*)d_in[18];
    const float* ae3 = (const float*)d_in[19];
    const float* b3  = (const float*)d_in[20];
    const int* src = ei;
    const int* dst = ei + EE;
    float* outp = (float*)d_out;

    float *asrc, *adst, *ce;
    __half *hw, *act, *x16, *w1, *w2, *w3;
    int *deg, *rowptr, *cursor, *csr;
    cudaGetSymbolAddress((void**)&hw,     g_hw);
    cudaGetSymbolAddress((void**)&act,    g_act);
    cudaGetSymbolAddress((void**)&x16,    g_x16);
    cudaGetSymbolAddress((void**)&w1,     g_w1);
    cudaGetSymbolAddress((void**)&w2,     g_w2);
    cudaGetSymbolAddress((void**)&w3,     g_w3);
    cudaGetSymbolAddress((void**)&asrc,   g_asrc);
    cudaGetSymbolAddress((void**)&adst,   g_adst);
    cudaGetSymbolAddress((void**)&ce,     g_ce);
    cudaGetSymbolAddress((void**)&deg,    g_deg);
    cudaGetSymbolAddress((void**)&rowptr, g_rowptr);
    cudaGetSymbolAddress((void**)&cursor, g_cursor);
    cudaGetSymbolAddress((void**)&csr,    g_csr);

    cudaFuncSetAttribute(gemm_fp16<NH>, cudaFuncAttributeMaxDynamicSharedMemorySize, GSMEM);
    cudaFuncSetAttribute(gemm_fp16<1>,  cudaFuncAttributeMaxDynamicSharedMemorySize, GSMEM);

    const int MB = (NN + 127) / 128;

    // prep + CSR build; launch #3 is the layer-1 GEMM (ncu captures idx 3)
    transpose_h<<<dim3((NN + 31) / 32, SEQL / 32), dim3(32, 8)>>>(x, x16);      // 0
    conv_w<<<(SEQL * HC + 255) / 256, 256>>>(W1, w1, SEQL * HC);                // 1
    zero_deg<<<(NN + 255) / 256, 256>>>(deg);                                   // 2
    gemm_fp16<NH><<<dim3(HC / 128, MB), 256, GSMEM>>>(x16, w1, hw, NN, SEQL, HC,
                                                      as1, ad1, asrc, adst);    // 3
    count_deg<<<(EE + 255) / 256, 256>>>(dst, deg);                             // 4
    scan_rowptr<<<1, 1024>>>(deg, rowptr);                                      // 5
    init_cursor<<<(NN + 255) / 256, 256>>>(rowptr, cursor);
    scatter_csr<<<(EE + 255) / 256, 256>>>(dst, cursor, csr);
    conv_w<<<(HC * HC + 255) / 256, 256>>>(W2, w2, HC * HC);
    conv_w<<<(HC * OUTC + 255) / 256, 256>>>(W3, w3, HC * OUTC);
    ce_all<<<1, 32>>>(We1, ae1, We2, ae2, We3, ae3, ce);

    // ---------------- Layer 1 ------------------------------------------------
    agg_fused<HIDC, NH, true, true><<<NN, HC / 8>>>(rowptr, csr, src, hw, asrc, adst, ew, ce, b1, nullptr, act);

    // ---------------- Layer 2 ------------------------------------------------
    gemm_fp16<NH><<<dim3(HC / 128, MB), 256, GSMEM>>>(act, w2, hw, NN, HC, HC,
                                                      as2, ad2, asrc, adst);
    agg_fused<HIDC, NH, true, true><<<NN, HC / 8>>>(rowptr, csr, src, hw, asrc, adst, ew, ce + 8, b2, nullptr, act);

    // ---------------- Layer 3 (heads=1, concat=False -> mean = identity) -----
    zero_ad<<<(NN + 255) / 256, 256>>>(asrc, adst);
    gemm_fp16<1><<<dim3(OUTC / 128, MB), 256, GSMEM>>>(act, w3, hw, NN, HC, OUTC,
                                                       as3, ad3, asrc, adst);
    agg_fused<OUTC, 1, false, false><<<NN, OUTC / 8>>>(rowptr, csr, src, hw, asrc, adst, ew, ce + 16, b3, outp, nullptr);
}